// round 16
// baseline (speedup 1.0000x reference)
#include <cuda_runtime.h>
#include <cuda_fp16.h>
#include <cstdint>

#define DH 128
#define BM 128
#define BN 64
#define NT 256
#define MAXB 32
#define MAXN 2048

// ---------------- preprocessed operands (device scratch) ----------------
// Q pre-scaled by 1/sqrt(d)*log2(e) and rounded to fp16; K, V^T fp16
__device__ __half g_QH[(size_t)MAXB * MAXN * DH];
__device__ __half g_KH[(size_t)MAXB * MAXN * DH];
__device__ __half g_VTH[(size_t)MAXB * DH * MAXN];   // [b][d][k]

// ---------------- persistent work queue ----------------
__device__ int g_ticket;
__device__ int g_order[MAXB];

// ---------------- PTX helpers (baseline ISA only) ----------------
__device__ __forceinline__ uint32_t smem_u32(const void* p) {
    uint32_t a;
    asm("{ .reg .u64 t; cvta.to.shared.u64 t, %1; cvt.u32.u64 %0, t; }" : "=r"(a) : "l"(p));
    return a;
}
__device__ __forceinline__ float ex2f(float x) {
    float y; asm("ex2.approx.f32 %0, %1;" : "=f"(y) : "f"(x)); return y;
}
// packed fp16 exp2
#define EX2H2(d, a) asm("ex2.approx.f16x2 %0, %1;" : "=r"(d) : "r"(a))
// pack two fp32 -> f16x2 {lo = x0, hi = x1}
#define CVTH2(d, x1, x0) asm("cvt.rn.f16x2.f32 %0, %1, %2;" : "=r"(d) : "f"(x1), "f"(x0))

#define MMA16816(d, a, b0, b1) \
    asm volatile("mma.sync.aligned.m16n8k16.row.col.f32.f16.f16.f32 " \
        "{%0,%1,%2,%3}, {%4,%5,%6,%7}, {%8,%9}, {%0,%1,%2,%3};" \
        : "+f"((d)[0]), "+f"((d)[1]), "+f"((d)[2]), "+f"((d)[3]) \
        : "r"((a)[0]), "r"((a)[1]), "r"((a)[2]), "r"((a)[3]), "r"(b0), "r"(b1))

#define LDSM4(r, addr) \
    asm volatile("ldmatrix.sync.aligned.m8n8.x4.shared.b16 {%0,%1,%2,%3}, [%4];" \
        : "=r"((r)[0]), "=r"((r)[1]), "=r"((r)[2]), "=r"((r)[3]) : "r"(addr))

#define CPA16(dst, src) \
    asm volatile("cp.async.cg.shared.global [%0], [%1], 16;" \
        :: "r"(dst), "l"(src) : "memory")
#define CPA_COMMIT() asm volatile("cp.async.commit_group;" ::: "memory")
#define CPA_WAIT0()  asm volatile("cp.async.wait_group 0;" ::: "memory")

// ---------------- smem layout (bytes) ----------------
#define SM_QH    0
#define SM_STAGE 32768
#define STAGE_SZ 32768
#define ST_KH    0
#define ST_VH    16384
#define SM_TOTAL (SM_STAGE + 2 * STAGE_SZ)   // 98304 = 96KB

__device__ __forceinline__ uint32_t q_off(int c, int row) {
    return (uint32_t)(c * 2048 + ((row * 16) ^ ((c & 7) << 4)));
}
__device__ __forceinline__ uint32_t k_off(int c, int key) {
    return (uint32_t)(c * 1024 + ((key * 16) ^ ((c & 7) << 4)));
}
__device__ __forceinline__ uint32_t v_off(int kc, int d) {
    return (uint32_t)(kc * 2048 + ((d * 16) ^ ((kc & 7) << 4)));
}

// ---------------- preprocessing: Q (scaled) and K fp32 -> fp16 ----------------
__global__ void prep_qk(const float* __restrict__ Q, const float* __restrict__ K,
                        int n4q, int n4k) {
    const float C = 0.08838834764831845f * 1.4426950408889634f;  // 1/sqrt(128)*log2(e)
    int i = blockIdx.x * blockDim.x + threadIdx.x;
    if (i < n4q) {
        float4 v = ((const float4*)Q)[i];
        __half2* dst = (__half2*)g_QH;
        dst[2 * i]     = __floats2half2_rn(v.x * C, v.y * C);
        dst[2 * i + 1] = __floats2half2_rn(v.z * C, v.w * C);
    } else if (i < n4q + n4k) {
        int idx = i - n4q;
        float4 v = ((const float4*)K)[idx];
        __half2* dst = (__half2*)g_KH;
        dst[2 * idx]     = __floats2half2_rn(v.x, v.y);
        dst[2 * idx + 1] = __floats2half2_rn(v.z, v.w);
    }
}
#define VT_STRIDE 133
__global__ void prep_vt(const float* __restrict__ V, int Nk) {
    extern __shared__ float ts[];   // [128][133]
    int tid = threadIdx.x;
    int b = blockIdx.y, k0 = blockIdx.x * 128;
    #pragma unroll
    for (int t = 0; t < 16; t++) {
        int lin = tid + 256 * t;
        int kk = lin >> 5, c4 = lin & 31;
        float4 v = *(const float4*)(V + ((size_t)b * Nk + k0 + kk) * DH + 4 * c4);
        ts[kk * VT_STRIDE + 4 * c4 + 0] = v.x;
        ts[kk * VT_STRIDE + 4 * c4 + 1] = v.y;
        ts[kk * VT_STRIDE + 4 * c4 + 2] = v.z;
        ts[kk * VT_STRIDE + 4 * c4 + 3] = v.w;
    }
    __syncthreads();
    #pragma unroll
    for (int t = 0; t < 8; t++) {
        int lin = tid + 256 * t;
        int d = lin >> 4, kc = lin & 15;
        union { uint4 q; __half2 p[4]; } uh;
        #pragma unroll
        for (int u = 0; u < 8; u += 2) {
            float x0 = ts[(8 * kc + u + 0) * VT_STRIDE + d];
            float x1 = ts[(8 * kc + u + 1) * VT_STRIDE + d];
            uh.p[u >> 1] = __floats2half2_rn(x0, x1);
        }
        size_t o = ((size_t)(b * DH + d)) * Nk + k0 + 8 * kc;
        *(uint4*)(g_VTH + o) = uh.q;
    }
}

// ---- LPT order: sort batches by descending valid length (deterministic) ----
__global__ void prep_order(const int* __restrict__ vlen, int B) {
    if (threadIdx.x == 0) {
        int val[MAXB], id[MAXB];
        for (int i = 0; i < B; i++) { val[i] = vlen[i]; id[i] = i; }
        for (int i = 0; i < B; i++) {
            int best = i;
            for (int jj = i + 1; jj < B; jj++)
                if (val[jj] > val[best] || (val[jj] == val[best] && id[jj] < id[best]))
                    best = jj;
            int tv = val[i]; val[i] = val[best]; val[best] = tv;
            int ti = id[i];  id[i]  = id[best];  id[best]  = ti;
            g_order[i] = id[i];
        }
        g_ticket = 0;
    }
}

// ---------------- stage loader (K + V^T fp16, cp.async, 256 thr) ----------------
__device__ __forceinline__ void load_stage(uint32_t sb, int buf, int b, int kb,
                                           int Nk, int tid) {
    uint32_t st = sb + SM_STAGE + (uint32_t)buf * STAGE_SZ;
    #pragma unroll
    for (int t = 0; t < 4; t++) {
        int idx = tid + NT * t;          // [chunk 0..15][key 0..63]
        int c = idx >> 6, key = idx & 63;
        size_t off = ((size_t)b * Nk + kb + key) * DH + 8 * c;
        CPA16(st + ST_KH + k_off(c, key), (uint64_t)__cvta_generic_to_global(g_KH + off));
    }
    #pragma unroll
    for (int t = 0; t < 4; t++) {
        int idx = tid + NT * t;          // [kc 0..7][dim 0..127]
        int kc = idx >> 7, dd = idx & 127;
        size_t off = ((size_t)b * DH + dd) * Nk + kb + 8 * kc;
        CPA16(st + ST_VH + v_off(kc, dd), (uint64_t)__cvta_generic_to_global(g_VTH + off));
    }
}

// ---------------- main kernel: persistent 8-warp HMMA flash attention ----------------
// Same math as R14/R15 (pre-scaled Q, fp16 softmax, ones-MMA denominator).
// This round: MANUAL PHASE INTERLEAVING — asm volatile forces program-order issue,
// so QK(1) is hand-interleaved with PV(0) to cover both softmax dependency chains
// and fragment-load latency with independent MMA issue.
__global__ void __launch_bounds__(NT, 1)
attn_mma_kernel(const int* __restrict__ vlen, float* __restrict__ Out,
                int Nq, int Nk, int nItems, int qpb)
{
    extern __shared__ char smem[];
    __shared__ int s_item;
    const uint32_t sb = smem_u32(smem);
    const int tid = threadIdx.x, lane = tid & 31, g = tid >> 5;   // warp = row group
    const uint32_t ONE = 0x3C003C00u;    // fp16 {1.0, 1.0}

    const int lr   = lane & 7;
    const int half = (lane >> 3) & 1;
    const int cksel = lane >> 4;
    const int t4 = lane & 3, gg = lane >> 2;
    const int rowq = 16 * g + lr + 8 * half;     // ldmatrix row for Q A-frags
    const int rkv  = lr + 8 * half;              // ldmatrix row base for K/V B-frags

    for (;;) {
        if (tid == 0) s_item = atomicAdd(&g_ticket, 1);
        __syncthreads();                         // broadcast item; prev item fully done
        const int item = s_item;
        if (item >= nItems) break;
        const int b  = g_order[item / qpb];
        const int qb = item % qpb;
        const int valid = vlen[b];
        const int ntiles = (valid + BN - 1) / BN;

        // ---- Q tile + first stage via cp.async ----
        {
            size_t qbase = ((size_t)b * Nq + (size_t)qb * BM) * DH;
            #pragma unroll
            for (int t = 0; t < 8; t++) {
                int idx = tid + NT * t;          // [chunk 0..15][row 0..127]
                int c = idx >> 7, q = idx & 127;
                size_t off = qbase + (size_t)q * DH + 8 * c;
                CPA16(sb + SM_QH + q_off(c, q), (uint64_t)__cvta_generic_to_global(g_QH + off));
            }
            load_stage(sb, 0, b, 0, Nk, tid);
            CPA_COMMIT();
        }

        float O[16][4];
        #pragma unroll
        for (int i = 0; i < 16; i++)
            #pragma unroll
            for (int c = 0; c < 4; c++) O[i][c] = 0.0f;
        float Lacc[4] = {0.0f, 0.0f, 0.0f, 0.0f};
        uint32_t aH[8][4];                       // item-resident Q fragments

        for (int j = 0; j < ntiles; j++) {
            CPA_WAIT0();
            __syncthreads();   // stage j ready; PV(j-1) complete in all warps

            if (j == 0) {      // Q fragments -> registers, once per item
                #pragma unroll
                for (int ck = 0; ck < 8; ck++)
                    LDSM4(aH[ck], sb + SM_QH + q_off(2 * ck + cksel, rowq));
            }

            // prefetch next stage (targets buffer freed by PV(j-1))
            if (j + 1 < ntiles) { load_stage(sb, (j + 1) & 1, b, (j + 1) * BN, Nk, tid); CPA_COMMIT(); }

            const uint32_t st = sb + SM_STAGE + (uint32_t)(j & 1) * STAGE_SZ;
            const int lim = valid - j * BN;
            const bool partial = (lim < BN);

            // ================= phase 1: QK(0), keys 0..31 =================
            float S0[4][4];
            #pragma unroll
            for (int n = 0; n < 4; n++)
                #pragma unroll
                for (int c = 0; c < 4; c++) S0[n][c] = 0.0f;
            {
                uint32_t kf[2][8];
                LDSM4(&kf[0][0], st + ST_KH + k_off(cksel, rkv));
                LDSM4(&kf[0][4], st + ST_KH + k_off(cksel, 16 + rkv));
                #pragma unroll
                for (int ck = 0; ck < 8; ck++) {
                    const int cur = ck & 1, nxt = cur ^ 1;
                    if (ck < 7) {
                        const int cqn = 2 * (ck + 1) + cksel;
                        LDSM4(&kf[nxt][0], st + ST_KH + k_off(cqn, rkv));
                        LDSM4(&kf[nxt][4], st + ST_KH + k_off(cqn, 16 + rkv));
                    }
                    MMA16816(S0[0], aH[ck], kf[cur][0], kf[cur][2]);
                    MMA16816(S0[1], aH[ck], kf[cur][1], kf[cur][3]);
                    MMA16816(S0[2], aH[ck], kf[cur][4], kf[cur][6]);
                    MMA16816(S0[3], aH[ck], kf[cur][5], kf[cur][7]);
                }
            }

            // ================= phase 2: softmax(0) + l-MMA(0) =================
            uint32_t P0[2][4];
            if (!partial) {
                #pragma unroll
                for (int n = 0; n < 4; n++) {
                    uint32_t c01, c23;
                    CVTH2(c01, S0[n][1], S0[n][0]);
                    CVTH2(c23, S0[n][3], S0[n][2]);
                    EX2H2(P0[n >> 1][(n & 1) * 2 + 0], c01);
                    EX2H2(P0[n >> 1][(n & 1) * 2 + 1], c23);
                }
            } else {
                #pragma unroll
                for (int n = 0; n < 4; n++) {
                    const int k0 = 8 * n + 2 * t4;
                    float p0 = (k0     < lim) ? ex2f(S0[n][0]) : 0.0f;
                    float p1 = (k0 + 1 < lim) ? ex2f(S0[n][1]) : 0.0f;
                    float p2 = (k0     < lim) ? ex2f(S0[n][2]) : 0.0f;
                    float p3 = (k0 + 1 < lim) ? ex2f(S0[n][3]) : 0.0f;
                    CVTH2(P0[n >> 1][(n & 1) * 2 + 0], p1, p0);
                    CVTH2(P0[n >> 1][(n & 1) * 2 + 1], p3, p2);
                }
            }
            MMA16816(Lacc, P0[0], ONE, ONE);
            MMA16816(Lacc, P0[1], ONE, ONE);

            // ===== phase 3: INTERLEAVED QK(1) [keys 32..63] + PV(0) =====
            // step i: QK-iter i (2 LDSM + 4 MMA) + PV(0) half-batch i (2 LDSM + 4 MMA)
            float S1[4][4];
            #pragma unroll
            for (int n = 0; n < 4; n++)
                #pragma unroll
                for (int c = 0; c < 4; c++) S1[n][c] = 0.0f;
            {
                uint32_t kf[2][8], vf[2][8];
                LDSM4(&kf[0][0], st + ST_KH + k_off(cksel, 32 + rkv));
                LDSM4(&kf[0][4], st + ST_KH + k_off(cksel, 48 + rkv));
                // PV(0) half-batch 0: bi=0 (kc base 0, dim-half 0), q4 in {0,1}
                LDSM4(&vf[0][0], st + ST_VH + v_off(cksel, rkv));
                LDSM4(&vf[0][4], st + ST_VH + v_off(cksel, 16 + rkv));
                #pragma unroll
                for (int i = 0; i < 8; i++) {
                    const int cur = i & 1, nxt = cur ^ 1;
                    if (i < 7) {
                        // next QK chunk
                        const int cqn = 2 * (i + 1) + cksel;
                        LDSM4(&kf[nxt][0], st + ST_KH + k_off(cqn, 32 + rkv));
                        LDSM4(&kf[nxt][4], st + ST_KH + k_off(cqn, 48 + rkv));
                        // next PV(0) half-batch: hb = i+1
                        const int hbn = i + 1;
                        const int bin = hbn >> 1, qpn = hbn & 1;
                        const int kcn = 2 * (bin >> 1) + cksel;     // mp=0
                        const int dbn = 64 * (bin & 1) + 32 * qpn;
                        LDSM4(&vf[nxt][0], st + ST_VH + v_off(kcn, dbn + rkv));
                        LDSM4(&vf[nxt][4], st + ST_VH + v_off(kcn, dbn + 16 + rkv));
                    }
                    // QK(1) MMAs for chunk i
                    MMA16816(S1[0], aH[i], kf[cur][0], kf[cur][2]);
                    MMA16816(S1[1], aH[i], kf[cur][1], kf[cur][3]);
                    MMA16816(S1[2], aH[i], kf[cur][4], kf[cur][6]);
                    MMA16816(S1[3], aH[i], kf[cur][5], kf[cur][7]);
                    // PV(0) MMAs for half-batch i
                    const int bi = i >> 1, qp = i & 1;
                    const int h2 = bi & 1, mmp = bi >> 1;
                    const int n0 = 8 * h2 + 4 * qp;                 // q4 = 2qp, 2qp+1
                    MMA16816(O[n0],     P0[mmp], vf[cur][0], vf[cur][2]);
                    MMA16816(O[n0 + 1], P0[mmp], vf[cur][1], vf[cur][3]);
                    MMA16816(O[n0 + 2], P0[mmp], vf[cur][4], vf[cur][6]);
                    MMA16816(O[n0 + 3], P0[mmp], vf[cur][5], vf[cur][7]);
                }
            }

            // ================= phase 4: softmax(1) + l-MMA(1) =================
            uint32_t P1[2][4];
            if (!partial) {
                #pragma unroll
                for (int n = 0; n < 4; n++) {
                    uint32_t c01, c23;
                    CVTH2(c01, S1[n][1], S1[n][0]);
                    CVTH2(c23, S1[n][3], S1[n][2]);
                    EX2H2(P1[n >> 1][(n & 1) * 2 + 0], c01);
                    EX2H2(P1[n >> 1][(n & 1) * 2 + 1], c23);
                }
            } else {
                #pragma unroll
                for (int n = 0; n < 4; n++) {
                    const int k0 = 32 + 8 * n + 2 * t4;
                    float p0 = (k0     < lim) ? ex2f(S1[n][0]) : 0.0f;
                    float p1 = (k0 + 1 < lim) ? ex2f(S1[n][1]) : 0.0f;
                    float p2 = (k0     < lim) ? ex2f(S1[n][2]) : 0.0f;
                    float p3 = (k0 + 1 < lim) ? ex2f(S1[n][3]) : 0.0f;
                    CVTH2(P1[n >> 1][(n & 1) * 2 + 0], p1, p0);
                    CVTH2(P1[n >> 1][(n & 1) * 2 + 1], p3, p2);
                }
            }
            MMA16816(Lacc, P1[0], ONE, ONE);
            MMA16816(Lacc, P1[1], ONE, ONE);

            // ================= phase 5: PV(1), half-batch pipelined =================
            {
                uint32_t vf[2][8];
                // hb=0: bi=0 -> kc = 2*(2*1 + 0) + cksel = 4 + cksel, dim-half 0, q4 {0,1}
                LDSM4(&vf[0][0], st + ST_VH + v_off(4 + cksel, rkv));
                LDSM4(&vf[0][4], st + ST_VH + v_off(4 + cksel, 16 + rkv));
                #pragma unroll
                for (int i = 0; i < 8; i++) {
                    const int cur = i & 1, nxt = cur ^ 1;
                    if (i < 7) {
                        const int hbn = i + 1;
                        const int bin = hbn >> 1, qpn = hbn & 1;
                        const int kcn = 2 * (2 + (bin >> 1)) + cksel;  // mp=1
                        const int dbn = 64 * (bin & 1) + 32 * qpn;
                        LDSM4(&vf[nxt][0], st + ST_VH + v_off(kcn, dbn + rkv));
                        LDSM4(&vf[nxt][4], st + ST_VH + v_off(kcn, dbn + 16 + rkv));
                    }
                    const int bi = i >> 1, qp = i & 1;
                    const int h2 = bi & 1, mmp = bi >> 1;
                    const int n0 = 8 * h2 + 4 * qp;
                    MMA16816(O[n0],     P1[mmp], vf[cur][0], vf[cur][2]);
                    MMA16816(O[n0 + 1], P1[mmp], vf[cur][1], vf[cur][3]);
                    MMA16816(O[n0 + 2], P1[mmp], vf[cur][4], vf[cur][6]);
                    MMA16816(O[n0 + 3], P1[mmp], vf[cur][5], vf[cur][7]);
                }
            }
        }

        // ---- epilogue: O / l -> global (fp32), warp-local; l from ones-MMA ----
        const float inv0 = 1.0f / Lacc[0], inv1 = 1.0f / Lacc[2];
        const int qg = qb * BM + 16 * g + gg;
        float* out0 = Out + ((size_t)b * Nq + qg) * DH;
        float* out1 = out0 + 8 * DH;
        #pragma unroll
        for (int n = 0; n < 16; n++) {
            const int col = 8 * n + 2 * t4;
            *(float2*)(out0 + col) = make_float2(O[n][0] * inv0, O[n][1] * inv0);
            *(float2*)(out1 + col) = make_float2(O[n][2] * inv1, O[n][3] * inv1);
        }
    }
}

// ---------------- launch ----------------
extern "C" void kernel_launch(void* const* d_in, const int* in_sizes, int n_in,
                              void* d_out, int out_size) {
    const float* Q  = (const float*)d_in[0];
    const float* K  = (const float*)d_in[1];
    const float* V  = (const float*)d_in[2];
    const int* vlen = (const int*)d_in[3];
    float* Out = (float*)d_out;

    int B  = in_sizes[3];
    int Nq = in_sizes[0] / (B * DH);
    int Nk = in_sizes[1] / (B * DH);

    int n4q = in_sizes[0] / 4;
    int n4k = in_sizes[1] / 4;

    int nsm = 148;
    cudaDeviceGetAttribute(&nsm, cudaDevAttrMultiProcessorCount, 0);

    cudaFuncSetAttribute(prep_vt, cudaFuncAttributeMaxDynamicSharedMemorySize,
                         128 * VT_STRIDE * 4);
    cudaFuncSetAttribute(attn_mma_kernel, cudaFuncAttributeMaxDynamicSharedMemorySize,
                         SM_TOTAL);

    prep_qk<<<(n4q + n4k + 255) / 256, 256>>>(Q, K, n4q, n4k);
    dim3 gv(Nk / 128, B);
    prep_vt<<<gv, 256, 128 * VT_STRIDE * 4>>>(V, Nk);
    prep_order<<<1, 32>>>(vlen, B);

    const int qpb = Nq / BM;
    const int nItems = B * qpb;
    int grid = (nsm < nItems) ? nsm : nItems;
    attn_mma_kernel<<<grid, NT, SM_TOTAL>>>(vlen, Out, Nq, Nk, nItems, qpb);
}